// round 6
// baseline (speedup 1.0000x reference)
#include <cuda_runtime.h>
#include <math.h>

// Problem constants
#define MDIM 63
#define NW1 32256   // 32*16*63
#define NW2 16128   // 16*16*63
#define NW3 1008    // 16*1*63

// Scratch (__device__ globals; no allocation)
__device__ float g_C1[32 * 64 * 32];  // stage1 tables: [f][t][o*2 + {P,S}]   256 KB
__device__ float g_C2[16 * 64 * 32];  // stage2                               128 KB
__device__ float g_C3[16 * 64 * 2];   // stage3 (O=1)                           8 KB
__device__ float g_bias1[16];
__device__ float g_bias2[16];
__device__ float g_bias3[1];
__device__ double g_klpart[4];

__device__ __forceinline__ float softplusf(float r) {
    return (r > 15.f) ? r : log1pf(__expf(r));
}
__device__ __forceinline__ float clamp80(float v) {
    return fminf(fmaxf(v, -80.f), 80.f);
}
__device__ __forceinline__ int tidx(float xc) {
    int t = __float2int_rd(xc * 64.f);
    return min(63, max(0, t));
}

// ---------------------------------------------------------------------------
// prep_all: 54 blocks x 256 threads.
//  blocks 0-48 : W = mu + softplus(rho)*eps (smem) -> V = Rinv^T-dot (smem)
//                -> fp64 prefix/suffix scans (even/odd ILP) -> g_C{1,2,3}.
//                Each block owns 16 consecutive global rows; stage boundaries
//                (rows 512, 768) are multiples of 16, so blocks are stage-pure.
//  block 49    : summed biases.
//  blocks 50-53: KL partials (deterministic fixed-order, fp64).
// Table entry layout per (f,t): 2*O floats; pair (o*2+0, o*2+1) = {Pref, Suf}:
//   Pref[t] = sum_{m<=t} exp(+u_m) V_m   (main kernel scales by exp(-x))
//   Suf [t] = sum_{m> t} exp(-u_m) V_m   (main kernel scales by exp(+x))
// ---------------------------------------------------------------------------
__global__ void __launch_bounds__(256) prep_all(
    const float* __restrict__ U, const float* __restrict__ Rinv,
    const float* __restrict__ mw1, const float* __restrict__ rw1, const float* __restrict__ ew1,
    const float* __restrict__ mb1, const float* __restrict__ rb1, const float* __restrict__ eb1,
    const float* __restrict__ mw2, const float* __restrict__ rw2, const float* __restrict__ ew2,
    const float* __restrict__ mb2, const float* __restrict__ rb2, const float* __restrict__ eb2,
    const float* __restrict__ mw3, const float* __restrict__ rw3, const float* __restrict__ ew3,
    const float* __restrict__ mb3, const float* __restrict__ rb3, const float* __restrict__ eb3)
{
    const int blk = blockIdx.x;
    const int tid = threadIdx.x;

    if (blk < 49) {
        const float *mu, *rho, *eps; int baserow; float* C; int O;
        if (blk < 32)      { mu = mw1; rho = rw1; eps = ew1; baserow = 0;   C = g_C1; O = 16; }
        else if (blk < 48) { mu = mw2; rho = rw2; eps = ew2; baserow = 512; C = g_C2; O = 16; }
        else               { mu = mw3; rho = rw3; eps = ew3; baserow = 768; C = g_C3; O = 1;  }
        const int row0 = blk * 16;                  // global row base
        const int loff = (row0 - baserow) * MDIM;   // flat offset within stage arrays

        __shared__ float  sW[16 * MDIM];
        __shared__ float  sV[16 * MDIM];
        __shared__ double seu[64], sev[64];         // exp(+-u_m), m = 1..63

        if (tid < MDIM) {
            double u = (double)U[tid];
            seu[tid + 1] = exp(u);
            sev[tid + 1] = exp(-u);
        }
        for (int i = tid; i < 16 * MDIM; i += 256) {
            int j = loff + i;
            sW[i] = fmaf(softplusf(rho[j]), eps[j], mu[j]);
        }
        __syncthreads();

        for (int i = tid; i < 16 * MDIM; i += 256) {
            int r = i / MDIM, m = i - r * MDIM;
            const float* w  = &sW[r * MDIM];
            const float* rv = Rinv + m * MDIM;
            float s0 = 0.f, s1 = 0.f, s2 = 0.f, s3 = 0.f;
            int n = 0;
            for (; n + 3 < MDIM; n += 4) {
                s0 = fmaf(w[n + 0], __ldg(rv + n + 0), s0);
                s1 = fmaf(w[n + 1], __ldg(rv + n + 1), s1);
                s2 = fmaf(w[n + 2], __ldg(rv + n + 2), s2);
                s3 = fmaf(w[n + 3], __ldg(rv + n + 3), s3);
            }
            for (; n < MDIM; n++) s0 = fmaf(w[n], __ldg(rv + n), s0);
            sV[i] = (s0 + s1) + (s2 + s3);
        }
        __syncthreads();

        if (tid < 16) {
            int q = (row0 - baserow) + tid;         // stage-local row
            int f, o;
            if (O == 16) { f = q >> 4; o = q & 15; } else { f = q; o = 0; }
            const float* V = &sV[tid * MDIM];
            const int stride = 2 * O;
            float* Cp = C + f * 64 * stride + o * 2;

            // ---- prefix scan, even/odd accumulator chains (2-way ILP) ----
            // Pref[m] = sum_{j<=m} seu[j]*V[j-1]
            {
                double a0 = 0.0, a1 = 0.0;          // a1: odd m, a0: even m
                Cp[0] = 0.f;
                #pragma unroll 4
                for (int m = 1; m <= 61; m += 2) {
                    a1 += seu[m]     * (double)V[m - 1];
                    Cp[m * stride] = (float)(a0 + a1);
                    a0 += seu[m + 1] * (double)V[m];
                    Cp[(m + 1) * stride] = (float)(a0 + a1);
                }
                a1 += seu[63] * (double)V[62];
                Cp[63 * stride] = (float)(a0 + a1);
            }

            // ---- suffix scan, even/odd accumulator chains (2-way ILP) ----
            // Suf[t] = sum_{m>t} sev[m]*V[m-1]   (written at t = m-1)
            {
                double s0 = 0.0, s1 = 0.0;
                Cp[63 * stride + 1] = 0.f;
                #pragma unroll 4
                for (int m = 63; m >= 3; m -= 2) {
                    s1 += sev[m]     * (double)V[m - 1];
                    Cp[(m - 1) * stride + 1] = (float)(s0 + s1);
                    s0 += sev[m - 1] * (double)V[m - 2];
                    Cp[(m - 2) * stride + 1] = (float)(s0 + s1);
                }
                s1 += sev[1] * (double)V[0];
                Cp[0 * stride + 1] = (float)(s0 + s1);
            }
        }
    } else if (blk == 49) {
        if (tid < 16) {
            double a = 0.0;
            for (int f = 0; f < 32; f++) {
                int j = f * 16 + tid;
                a += (double)mb1[j] + (double)softplusf(rb1[j]) * (double)eb1[j];
            }
            g_bias1[tid] = (float)a;
        } else if (tid < 32) {
            int o = tid - 16;
            double a = 0.0;
            for (int f = 0; f < 16; f++) {
                int j = f * 16 + o;
                a += (double)mb2[j] + (double)softplusf(rb2[j]) * (double)eb2[j];
            }
            g_bias2[o] = (float)a;
        } else if (tid == 32) {
            double a = 0.0;
            for (int f = 0; f < 16; f++)
                a += (double)mb3[f] + (double)softplusf(rb3[f]) * (double)eb3[f];
            g_bias3[0] = (float)a;
        }
    } else {
        __shared__ double sh[256];
        int kb = blk - 50;
        int vt = kb * 256 + tid;            // 0..1023
        const float* mus[6]  = {mw1, mb1, mw2, mb2, mw3, mb3};
        const float* rhos[6] = {rw1, rb1, rw2, rb2, rw3, rb3};
        const int ns[6] = {NW1, 512, NW2, 256, NW3, 16};
        double acc = 0.0;
        for (int a = 0; a < 6; a++) {
            const float* mu  = mus[a];
            const float* rho = rhos[a];
            int n = ns[a];
            for (int i = vt; i < n; i += 1024) {
                float s = softplusf(rho[i]);
                float m = mu[i];
                acc += (double)(0.5f * fmaf(s, s, m * m) - logf(s) - 0.5f);
            }
        }
        sh[tid] = acc;
        __syncthreads();
        for (int w = 128; w > 0; w >>= 1) {
            if (tid < w) sh[tid] += sh[tid + w];
            __syncthreads();
        }
        if (tid == 0) g_klpart[kb] = sh[0];
    }
}

// ---------------------------------------------------------------------------
// Main kernel: block = 256 threads = 16 batch elements; lane group of 16 = one b.
// Phase 1 precomputes (exp(-x), exp(x), t*32) per (b,f) into smem (coalesced x
// reads, broadcast LDS.128 in the main loop -> no warp shuffles on hot path).
// ---------------------------------------------------------------------------
__global__ void __launch_bounds__(256) main_kernel(const float* __restrict__ x,
                                                   float* __restrict__ out,
                                                   int B, int out_size) {
    if (blockIdx.x == 0 && threadIdx.x == 0) {
        double k = ((g_klpart[0] + g_klpart[1]) + (g_klpart[2] + g_klpart[3]));
        out[out_size - 1] = (float)k;
    }

    __shared__ float4 s1[16][33];   // +1 float4 pad: adjacent b rows offset banks
    __shared__ float4 s2[16][17];

    const int tid = threadIdx.x;
    const int b0 = blockIdx.x * 16;

    // ---- phase 1: (ei, e, t*32) for all 16 b x 32 f of this block ----
    #pragma unroll
    for (int k = 0; k < 2; k++) {
        int i  = tid + k * 256;       // 0..511
        int bl = i >> 5, f = i & 31;
        int bsafe = min(b0 + bl, B - 1);
        float xc = clamp80(__ldg(x + bsafe * 32 + f));
        float e = __expf(xc), ei = __expf(-xc);
        int t = tidx(xc);
        s1[bl][f] = make_float4(ei, e, __int_as_float(t << 5), 0.f);
    }
    __syncthreads();

    const int lane = tid & 31;
    const int bl   = ((tid >> 5) << 1) | (lane >> 4);   // 0..15: batch elem in block
    const int o    = lane & 15;
    const int o2   = o << 1;
    const unsigned FULL = 0xffffffffu;

    // ---- stage 1 ----
    float h = g_bias1[o];
    const float* C1o = g_C1 + o2;
    #pragma unroll
    for (int f = 0; f < 32; f++) {
        float4 v = s1[bl][f];
        float2 c = *(const float2*)(C1o + (f << 11) + __float_as_int(v.z));
        h = fmaf(v.x, c.x, fmaf(v.y, c.y, h));   // ei*Pref + e*Suf
    }

    // ---- stage 2: publish own (ei, e, t*32), sync, consume broadcasts ----
    {
        float xs = clamp80(h);
        s2[bl][o] = make_float4(__expf(-xs), __expf(xs),
                                __int_as_float(tidx(xs) << 5), 0.f);
    }
    __syncthreads();

    float h2 = g_bias2[o];
    const float* C2o = g_C2 + o2;
    #pragma unroll
    for (int f = 0; f < 16; f++) {
        float4 v = s2[bl][f];
        float2 c = *(const float2*)(C2o + (f << 11) + __float_as_int(v.z));
        h2 = fmaf(v.x, c.x, fmaf(v.y, c.y, h2));
    }

    // ---- stage 3: lane o = feature o; 16-lane xor reduction ----
    float xc3 = clamp80(h2);
    int   t3  = tidx(xc3);
    float2 v3 = *(const float2*)&g_C3[((o << 6) + t3) << 1];
    float term = fmaf(__expf(-xc3), v3.x, __expf(xc3) * v3.y);

    #pragma unroll
    for (int w = 8; w; w >>= 1) term += __shfl_xor_sync(FULL, term, w);

    int b = b0 + bl;
    if (o == 0 && b < B) out[b] = term + g_bias3[0];
}

// ---------------------------------------------------------------------------
extern "C" void kernel_launch(void* const* d_in, const int* in_sizes, int n_in,
                              void* d_out, int out_size) {
    const float* x    = (const float*)d_in[0];
    const float* U    = (const float*)d_in[1];
    const float* Rinv = (const float*)d_in[2];
    const float* mw1 = (const float*)d_in[3],  *rw1 = (const float*)d_in[4];
    const float* mb1 = (const float*)d_in[5],  *rb1 = (const float*)d_in[6];
    const float* ew1 = (const float*)d_in[7],  *eb1 = (const float*)d_in[8];
    const float* mw2 = (const float*)d_in[9],  *rw2 = (const float*)d_in[10];
    const float* mb2 = (const float*)d_in[11], *rb2 = (const float*)d_in[12];
    const float* ew2 = (const float*)d_in[13], *eb2 = (const float*)d_in[14];
    const float* mw3 = (const float*)d_in[15], *rw3 = (const float*)d_in[16];
    const float* mb3 = (const float*)d_in[17], *rb3 = (const float*)d_in[18];
    const float* ew3 = (const float*)d_in[19], *eb3 = (const float*)d_in[20];

    int B = in_sizes[0] / 32;
    float* out = (float*)d_out;

    prep_all<<<54, 256>>>(U, Rinv,
                          mw1, rw1, ew1, mb1, rb1, eb1,
                          mw2, rw2, ew2, mb2, rb2, eb2,
                          mw3, rw3, ew3, mb3, rb3, eb3);
    int blocks = (B + 15) / 16;
    main_kernel<<<blocks, 256>>>(x, out, B, out_size);
}

// round 16
// speedup vs baseline: 1.4312x; 1.4312x over previous
#include <cuda_runtime.h>
#include <math.h>

// Problem constants
#define MDIM 63
#define NW1 32256   // 32*16*63
#define NW2 16128   // 16*16*63
#define NW3 1008    // 16*1*63
#define FULLM 0xffffffffu

// Scratch (__device__ globals; no allocation). 128B-aligned for vector loads.
__device__ __align__(128) float g_C1[32 * 64 * 32];  // [f][t][o*2+{P,S}] 256 KB
__device__ __align__(128) float g_C2[16 * 64 * 32];  // 128 KB
__device__ __align__(128) float g_C3[16 * 64 * 2];   // 8 KB
__device__ float g_bias1[16];
__device__ float g_bias2[16];
__device__ float g_bias3[1];
__device__ double g_klpart[4];

__device__ __forceinline__ float softplusf(float r) {
    return (r > 15.f) ? r : log1pf(__expf(r));
}
__device__ __forceinline__ float clamp80(float v) {
    return fminf(fmaxf(v, -80.f), 80.f);
}
__device__ __forceinline__ int tidx(float xc) {
    int t = __float2int_rd(xc * 64.f);
    return min(63, max(0, t));
}

// ---------------------------------------------------------------------------
// prep_all: 103 blocks x 256 threads.
//  blocks 0-97 : 8 rows each. W=mu+softplus(rho)*eps (smem) -> V (smem) ->
//                warp-parallel fp64 prefix/suffix scans (1 row per warp).
//                Stage boundaries at rows 512 (blk 64) and 768 (blk 96).
//  block 98    : summed biases.
//  blocks 99-102: KL partials (deterministic fixed-order, fp64).
// Table pair (o*2+0, o*2+1) per (f,t): {Pref, Suf}
//   Pref[t] = sum_{m<=t} exp(+u_m) V_m   (scaled by exp(-x) in main)
//   Suf [t] = sum_{m> t} exp(-u_m) V_m   (scaled by exp(+x) in main)
// ---------------------------------------------------------------------------
__global__ void __launch_bounds__(256) prep_all(
    const float* __restrict__ U, const float* __restrict__ Rinv,
    const float* __restrict__ mw1, const float* __restrict__ rw1, const float* __restrict__ ew1,
    const float* __restrict__ mb1, const float* __restrict__ rb1, const float* __restrict__ eb1,
    const float* __restrict__ mw2, const float* __restrict__ rw2, const float* __restrict__ ew2,
    const float* __restrict__ mb2, const float* __restrict__ rb2, const float* __restrict__ eb2,
    const float* __restrict__ mw3, const float* __restrict__ rw3, const float* __restrict__ ew3,
    const float* __restrict__ mb3, const float* __restrict__ rb3, const float* __restrict__ eb3)
{
    const int blk = blockIdx.x;
    const int tid = threadIdx.x;

    if (blk < 98) {
        const float *mu, *rho, *eps; int baserow; float* C; int O;
        if (blk < 64)      { mu = mw1; rho = rw1; eps = ew1; baserow = 0;   C = g_C1; O = 16; }
        else if (blk < 96) { mu = mw2; rho = rw2; eps = ew2; baserow = 512; C = g_C2; O = 16; }
        else               { mu = mw3; rho = rw3; eps = ew3; baserow = 768; C = g_C3; O = 1;  }
        const int row0 = blk * 8;                   // global row base
        const int loff = (row0 - baserow) * MDIM;   // flat offset within stage arrays

        __shared__ float  sW[8 * MDIM];
        __shared__ float  sV[8 * MDIM];
        __shared__ double seu[64], sev[64];         // exp(+-u_m), m = 1..63

        if (tid < MDIM) {
            double u = (double)U[tid];
            seu[tid + 1] = exp(u);
            sev[tid + 1] = exp(-u);
        }
        for (int i = tid; i < 8 * MDIM; i += 256) {
            int j = loff + i;
            sW[i] = fmaf(softplusf(rho[j]), eps[j], mu[j]);
        }
        __syncthreads();

        for (int i = tid; i < 8 * MDIM; i += 256) {
            int r = i / MDIM, m = i - r * MDIM;
            const float* w  = &sW[r * MDIM];
            const float* rv = Rinv + m * MDIM;
            float s0 = 0.f, s1 = 0.f, s2 = 0.f, s3 = 0.f;
            int n = 0;
            for (; n + 3 < MDIM; n += 4) {
                s0 = fmaf(w[n + 0], __ldg(rv + n + 0), s0);
                s1 = fmaf(w[n + 1], __ldg(rv + n + 1), s1);
                s2 = fmaf(w[n + 2], __ldg(rv + n + 2), s2);
                s3 = fmaf(w[n + 3], __ldg(rv + n + 3), s3);
            }
            for (; n < MDIM; n++) s0 = fmaf(w[n], __ldg(rv + n), s0);
            sV[i] = (s0 + s1) + (s2 + s3);
        }
        __syncthreads();

        // ---- warp-parallel fp64 scans: warp w owns row w ----
        {
            const int w    = tid >> 5;
            const int lane = tid & 31;
            const int q = (row0 - baserow) + w;     // stage-local row
            int f, o;
            if (O == 16) { f = q >> 4; o = q & 15; } else { f = q; o = 0; }
            const float* V = &sV[w * MDIM];
            const int stride = 2 * O;
            float* Cp = C + f * 64 * stride + o * 2;

            // prefix: Pref[m] = sum_{j<=m} seu[j]*V[j-1], m = 1..63
            {
                int ma = lane + 1;          // 1..32
                int mb = lane + 33;         // 33..64 (64 invalid)
                double ta = seu[ma] * (double)V[ma - 1];
                double tb = (mb <= MDIM) ? seu[mb] * (double)V[mb - 1] : 0.0;
                #pragma unroll
                for (int d = 1; d < 32; d <<= 1) {
                    double v = __shfl_up_sync(FULLM, ta, d);
                    if (lane >= d) ta += v;
                }
                double lowtot = __shfl_sync(FULLM, ta, 31);
                #pragma unroll
                for (int d = 1; d < 32; d <<= 1) {
                    double v = __shfl_up_sync(FULLM, tb, d);
                    if (lane >= d) tb += v;
                }
                tb += lowtot;
                Cp[ma * stride] = (float)ta;
                if (mb <= MDIM) Cp[mb * stride] = (float)tb;
                if (lane == 31) Cp[0] = 0.f;
            }
            // suffix: Suf[t] = sum_{m>t} sev[m]*V[m-1]; stored at t = m-1
            {
                int mar = 63 - lane;        // 63..32
                int mbr = 31 - lane;        // 31..0 (0 invalid)
                double ra = sev[mar] * (double)V[mar - 1];
                double rb = (mbr >= 1) ? sev[mbr] * (double)V[mbr - 1] : 0.0;
                #pragma unroll
                for (int d = 1; d < 32; d <<= 1) {
                    double v = __shfl_up_sync(FULLM, ra, d);
                    if (lane >= d) ra += v;
                }
                double hightot = __shfl_sync(FULLM, ra, 31);
                #pragma unroll
                for (int d = 1; d < 32; d <<= 1) {
                    double v = __shfl_up_sync(FULLM, rb, d);
                    if (lane >= d) rb += v;
                }
                rb += hightot;
                Cp[(mar - 1) * stride + 1] = (float)ra;
                if (mbr >= 1) Cp[(mbr - 1) * stride + 1] = (float)rb;
                if (lane == 31) Cp[63 * stride + 1] = 0.f;
            }
        }
    } else if (blk == 98) {
        if (tid < 16) {
            double a = 0.0;
            for (int f = 0; f < 32; f++) {
                int j = f * 16 + tid;
                a += (double)mb1[j] + (double)softplusf(rb1[j]) * (double)eb1[j];
            }
            g_bias1[tid] = (float)a;
        } else if (tid < 32) {
            int o = tid - 16;
            double a = 0.0;
            for (int f = 0; f < 16; f++) {
                int j = f * 16 + o;
                a += (double)mb2[j] + (double)softplusf(rb2[j]) * (double)eb2[j];
            }
            g_bias2[o] = (float)a;
        } else if (tid == 32) {
            double a = 0.0;
            for (int f = 0; f < 16; f++)
                a += (double)mb3[f] + (double)softplusf(rb3[f]) * (double)eb3[f];
            g_bias3[0] = (float)a;
        }
    } else {
        __shared__ double sh[256];
        int kb = blk - 99;
        int vt = kb * 256 + tid;            // 0..1023
        const float* mus[6]  = {mw1, mb1, mw2, mb2, mw3, mb3};
        const float* rhos[6] = {rw1, rb1, rw2, rb2, rw3, rb3};
        const int ns[6] = {NW1, 512, NW2, 256, NW3, 16};
        double acc = 0.0;
        for (int a = 0; a < 6; a++) {
            const float* muA  = mus[a];
            const float* rhoA = rhos[a];
            int n = ns[a];
            for (int i = vt; i < n; i += 1024) {
                float s = softplusf(rhoA[i]);
                float m = muA[i];
                acc += (double)(0.5f * fmaf(s, s, m * m) - logf(s) - 0.5f);
            }
        }
        sh[tid] = acc;
        __syncthreads();
        for (int w = 128; w > 0; w >>= 1) {
            if (tid < w) sh[tid] += sh[tid + w];
            __syncthreads();
        }
        if (tid == 0) g_klpart[kb] = sh[0];
    }
}

// ---------------------------------------------------------------------------
// Main kernel: block = 256 threads = 32 batch elements.
// Lane group of 8 = one b; each thread owns OUTPUT PAIR {2o, 2o+1} and gathers
// float4 {P(2o),S(2o),P(2o+1),S(2o+1)} per feature (LDG.128, 1 wavefront/group).
// ---------------------------------------------------------------------------
__global__ void __launch_bounds__(256) main_kernel(const float* __restrict__ x,
                                                   float* __restrict__ out,
                                                   int B, int out_size) {
    if (blockIdx.x == 0 && threadIdx.x == 0) {
        double k = ((g_klpart[0] + g_klpart[1]) + (g_klpart[2] + g_klpart[3]));
        out[out_size - 1] = (float)k;
    }

    __shared__ float4 s1[32][33];   // +1 pad: warp's 4 b-groups offset banks
    __shared__ float4 s2[32][17];

    const int tid = threadIdx.x;
    const int b0 = blockIdx.x * 32;

    // ---- phase 1: (ei, e, t*32) for all 32 b x 32 f of this block ----
    #pragma unroll
    for (int k = 0; k < 4; k++) {
        int i  = tid + k * 256;       // 0..1023
        int bl = i >> 5, f = i & 31;
        int bsafe = min(b0 + bl, B - 1);
        float xc = clamp80(__ldg(x + bsafe * 32 + f));
        float e = __expf(xc), ei = __expf(-xc);
        int t = tidx(xc);
        s1[bl][f] = make_float4(ei, e, __int_as_float(t << 5), 0.f);
    }
    __syncthreads();

    const int lane = tid & 31;
    const int o    = lane & 7;                        // output-pair index 0..7
    const int bl   = ((tid >> 5) << 2) | (lane >> 3); // 0..31: batch elem in block
    const int o4   = o << 2;

    // ---- stage 1 ----
    float ha = g_bias1[2 * o], hb = g_bias1[2 * o + 1];
    const float* C1o = g_C1 + o4;
    #pragma unroll
    for (int f = 0; f < 32; f++) {
        float4 v = s1[bl][f];
        float4 c = *(const float4*)(C1o + (f << 11) + __float_as_int(v.z));
        ha = fmaf(v.x, c.x, fmaf(v.y, c.y, ha));
        hb = fmaf(v.x, c.z, fmaf(v.y, c.w, hb));
    }

    // ---- stage 2: publish both owned stage-1 outputs, sync, consume ----
    {
        float xa = clamp80(ha), xb = clamp80(hb);
        s2[bl][2 * o]     = make_float4(__expf(-xa), __expf(xa),
                                        __int_as_float(tidx(xa) << 5), 0.f);
        s2[bl][2 * o + 1] = make_float4(__expf(-xb), __expf(xb),
                                        __int_as_float(tidx(xb) << 5), 0.f);
    }
    __syncthreads();

    float h2a = g_bias2[2 * o], h2b = g_bias2[2 * o + 1];
    const float* C2o = g_C2 + o4;
    #pragma unroll
    for (int f = 0; f < 16; f++) {
        float4 v = s2[bl][f];
        float4 c = *(const float4*)(C2o + (f << 11) + __float_as_int(v.z));
        h2a = fmaf(v.x, c.x, fmaf(v.y, c.y, h2a));
        h2b = fmaf(v.x, c.z, fmaf(v.y, c.w, h2b));
    }

    // ---- stage 3: thread handles features 2o, 2o+1; reduce over 8 lanes ----
    float xa = clamp80(h2a), xb = clamp80(h2b);
    int ta = tidx(xa), tb = tidx(xb);
    float2 va = *(const float2*)&g_C3[(((2 * o) << 6) + ta) << 1];
    float2 vb = *(const float2*)&g_C3[(((2 * o + 1) << 6) + tb) << 1];
    float term = fmaf(__expf(-xa), va.x, __expf(xa) * va.y)
               + fmaf(__expf(-xb), vb.x, __expf(xb) * vb.y);

    term += __shfl_xor_sync(FULLM, term, 4);
    term += __shfl_xor_sync(FULLM, term, 2);
    term += __shfl_xor_sync(FULLM, term, 1);

    int b = b0 + bl;
    if (o == 0 && b < B) out[b] = term + g_bias3[0];
}

// ---------------------------------------------------------------------------
extern "C" void kernel_launch(void* const* d_in, const int* in_sizes, int n_in,
                              void* d_out, int out_size) {
    const float* x    = (const float*)d_in[0];
    const float* U    = (const float*)d_in[1];
    const float* Rinv = (const float*)d_in[2];
    const float* mw1 = (const float*)d_in[3],  *rw1 = (const float*)d_in[4];
    const float* mb1 = (const float*)d_in[5],  *rb1 = (const float*)d_in[6];
    const float* ew1 = (const float*)d_in[7],  *eb1 = (const float*)d_in[8];
    const float* mw2 = (const float*)d_in[9],  *rw2 = (const float*)d_in[10];
    const float* mb2 = (const float*)d_in[11], *rb2 = (const float*)d_in[12];
    const float* ew2 = (const float*)d_in[13], *eb2 = (const float*)d_in[14];
    const float* mw3 = (const float*)d_in[15], *rw3 = (const float*)d_in[16];
    const float* mb3 = (const float*)d_in[17], *rb3 = (const float*)d_in[18];
    const float* ew3 = (const float*)d_in[19], *eb3 = (const float*)d_in[20];

    int B = in_sizes[0] / 32;
    float* out = (float*)d_out;

    prep_all<<<103, 256>>>(U, Rinv,
                           mw1, rw1, ew1, mb1, rb1, eb1,
                           mw2, rw2, ew2, mb2, rb2, eb2,
                           mw3, rw3, ew3, mb3, rb3, eb3);
    int blocks = (B + 31) / 32;
    main_kernel<<<blocks, 256>>>(x, out, B, out_size);
}